// round 1
// baseline (speedup 1.0000x reference)
#include <cuda_runtime.h>
#include <cuda_bf16.h>
#include <math.h>

// Problem constants
#define B_  64
#define T_  512
#define I_  512
#define H_  1024
#define G4  4096           // 4*H
#define BH  (B_*H_)        // 65536

// ---------------------------------------------------------------------------
// Device scratch (allocation-free rule: __device__ globals)
// ---------------------------------------------------------------------------
// xp[dir][t][b][g] : precomputed input projection + biases. 2*512*64*4096 fp32 = 1 GiB
__device__ float g_xp[(size_t)2 * T_ * B_ * G4];
// h double-buffer: [phase][dir*BH + b*H + j]
__device__ float g_h[2][2 * BH];
// c state: [dir*BH + b*H + j]
__device__ float g_c[2 * BH];

// ---------------------------------------------------------------------------
// Init: zero h(phase 0) and c
// ---------------------------------------------------------------------------
__global__ void init_state_kernel() {
    int i = blockIdx.x * blockDim.x + threadIdx.x;
    if (i < 2 * BH) {
        g_h[0][i] = 0.0f;
        g_c[i]    = 0.0f;
    }
}

// ---------------------------------------------------------------------------
// Input projection: xp[dir][t][b][g] = sum_i x[b][src_t][i] * w_ih[g][i] + (b_ih+b_hh)[g]
//   src_t = t (fw) or T-1-t (bw)
// Tiled SGEMM: CTA = (gtile 64 cols, t, dir), 64 rows (= all b), BK=16,
// 128 threads, 8x4 microtile.
// ---------------------------------------------------------------------------
__global__ void __launch_bounds__(128) input_proj_kernel(
    const float* __restrict__ x,
    const float* __restrict__ w_fw, const float* __restrict__ w_bw,
    const float* __restrict__ bi_fw, const float* __restrict__ bh_fw,
    const float* __restrict__ bi_bw, const float* __restrict__ bh_bw)
{
    const int gt  = blockIdx.x;    // 0..63  (64-wide tile over 4096 gate cols)
    const int t   = blockIdx.y;    // 0..511
    const int dir = blockIdx.z;    // 0..1

    const float* w     = dir ? w_bw : w_fw;
    const float* bi    = dir ? bi_bw : bi_fw;
    const float* bh    = dir ? bh_bw : bh_fw;
    const int    src_t = dir ? (T_ - 1 - t) : t;

    __shared__ float sA[16][68];   // [k][b], pad 68 (16B-aligned rows, conflict-reduced)
    __shared__ float sB[16][68];   // [k][g_local]

    const int tid = threadIdx.x;
    const int tr  = tid >> 4;      // 0..7  -> rows tr*8 .. tr*8+7
    const int tc  = tid & 15;      // 0..15 -> cols tc*4 .. tc*4+3

    float acc[8][4];
#pragma unroll
    for (int i = 0; i < 8; i++)
#pragma unroll
        for (int j = 0; j < 4; j++) acc[i][j] = 0.0f;

    const float* Abase = x + (size_t)src_t * I_;               // + b*(T_*I_) per row
    const float* Bbase = w + (size_t)(gt * 64) * I_;           // + n*I_ per col

    for (int k0 = 0; k0 < I_; k0 += 16) {
#pragma unroll 4
        for (int idx = tid; idx < 1024; idx += 128) {
            int kk = idx & 15, m = idx >> 4;
            sA[kk][m] = Abase[(size_t)m * (T_ * I_) + k0 + kk];
        }
#pragma unroll 4
        for (int idx = tid; idx < 1024; idx += 128) {
            int kk = idx & 15, n = idx >> 4;
            sB[kk][n] = Bbase[(size_t)n * I_ + k0 + kk];
        }
        __syncthreads();
#pragma unroll
        for (int kk = 0; kk < 16; kk++) {
            float4 a0 = *(const float4*)&sA[kk][tr * 8];
            float4 a1 = *(const float4*)&sA[kk][tr * 8 + 4];
            float4 bb = *(const float4*)&sB[kk][tc * 4];
            float a[8] = {a0.x, a0.y, a0.z, a0.w, a1.x, a1.y, a1.z, a1.w};
            float bv[4] = {bb.x, bb.y, bb.z, bb.w};
#pragma unroll
            for (int i = 0; i < 8; i++)
#pragma unroll
                for (int j = 0; j < 4; j++) acc[i][j] += a[i] * bv[j];
        }
        __syncthreads();
    }

    // epilogue: add fused bias, write xp
    const int gbase = gt * 64 + tc * 4;
    float bias[4];
#pragma unroll
    for (int j = 0; j < 4; j++) bias[j] = bi[gbase + j] + bh[gbase + j];

    float* outp = g_xp + (((size_t)dir * T_ + t) * B_) * G4;
#pragma unroll
    for (int i = 0; i < 8; i++) {
        int m = tr * 8 + i;
        float4 v = make_float4(acc[i][0] + bias[0], acc[i][1] + bias[1],
                               acc[i][2] + bias[2], acc[i][3] + bias[3]);
        *(float4*)(outp + (size_t)m * G4 + gbase) = v;
    }
}

// ---------------------------------------------------------------------------
// LSTM step t (one launch per timestep, both directions in one grid).
// CTA = (dir, jt) with jt in [0,64): owns gate columns {q*H + jt*16 + jj}
// for q=0..3, jj=0..15 -> a 64x64 GEMM tile (M=64 batch, K=1024) whose
// epilogue has all 4 gates for its 16 j-columns -> fused activation + state
// update + output write.
// ---------------------------------------------------------------------------
__global__ void __launch_bounds__(128) lstm_step_kernel(
    const float* __restrict__ w_fw, const float* __restrict__ w_bw,
    float* __restrict__ out, int t)
{
    const int bx  = blockIdx.x;    // 0..127
    const int dir = bx & 1;
    const int jt  = bx >> 1;       // 0..63

    const float* w     = dir ? w_bw : w_fw;
    const int    phase = t & 1;
    const float* hprev = g_h[phase]     + dir * BH;
    float*       hnext = g_h[phase ^ 1] + dir * BH;
    float*       cbuf  = g_c            + dir * BH;
    const float* xp    = g_xp + ((size_t)dir * T_ + t) * B_ * G4;

    __shared__ float sA[16][68];
    __shared__ float sB[16][68];
    __shared__ float sG[64][68];   // gates staging for activation phase

    const int tid = threadIdx.x;
    const int tr  = tid >> 4;      // 0..7
    const int tc  = tid & 15;      // 0..15

    float acc[8][4];
#pragma unroll
    for (int i = 0; i < 8; i++)
#pragma unroll
        for (int j = 0; j < 4; j++) acc[i][j] = 0.0f;

    for (int k0 = 0; k0 < H_; k0 += 16) {
#pragma unroll 4
        for (int idx = tid; idx < 1024; idx += 128) {
            int kk = idx & 15, m = idx >> 4;
            sA[kk][m] = hprev[m * H_ + k0 + kk];
        }
#pragma unroll 4
        for (int idx = tid; idx < 1024; idx += 128) {
            int kk = idx & 15, c = idx >> 4;
            int row = (c >> 4) * H_ + jt * 16 + (c & 15);
            sB[kk][c] = w[(size_t)row * H_ + k0 + kk];
        }
        __syncthreads();
#pragma unroll
        for (int kk = 0; kk < 16; kk++) {
            float4 a0 = *(const float4*)&sA[kk][tr * 8];
            float4 a1 = *(const float4*)&sA[kk][tr * 8 + 4];
            float4 bb = *(const float4*)&sB[kk][tc * 4];
            float a[8] = {a0.x, a0.y, a0.z, a0.w, a1.x, a1.y, a1.z, a1.w};
            float bv[4] = {bb.x, bb.y, bb.z, bb.w};
#pragma unroll
            for (int i = 0; i < 8; i++)
#pragma unroll
                for (int j = 0; j < 4; j++) acc[i][j] += a[i] * bv[j];
        }
        __syncthreads();
    }

    // stage gates (+xp) into smem so the activation phase sees all 4 gates per j
    {
        const int q  = tc >> 2;            // gate index of this thread's 4 cols
        const int jj = (tc & 3) * 4;       // j-offset of first col
        const int gcol = q * H_ + jt * 16 + jj;
#pragma unroll
        for (int i = 0; i < 8; i++) {
            int m = tr * 8 + i;
            float4 xv = *(const float4*)(xp + (size_t)m * G4 + gcol);
            sG[m][tc * 4 + 0] = acc[i][0] + xv.x;
            sG[m][tc * 4 + 1] = acc[i][1] + xv.y;
            sG[m][tc * 4 + 2] = acc[i][2] + xv.z;
            sG[m][tc * 4 + 3] = acc[i][3] + xv.w;
        }
    }
    __syncthreads();

    // activation + state update: 64 b x 16 j = 1024 cells, 8 per thread
#pragma unroll
    for (int p = tid; p < 1024; p += 128) {
        int b = p >> 4, j = p & 15;
        float ig = sG[b][j];
        float fg = sG[b][16 + j];
        float gg = sG[b][32 + j];
        float og = sG[b][48 + j];
        int jc = jt * 16 + j;

        float c_old = cbuf[b * H_ + jc];
        float si = 1.0f / (1.0f + expf(-ig));
        float sf = 1.0f / (1.0f + expf(-fg));
        float so = 1.0f / (1.0f + expf(-og));
        float cn = sf * c_old + si * tanhf(gg);
        float hn = so * tanhf(cn);

        cbuf[b * H_ + jc]  = cn;
        hnext[b * H_ + jc] = hn;
        out[((size_t)b * T_ + t) * (2 * H_) + dir * H_ + jc] = hn;
    }
}

// ---------------------------------------------------------------------------
// Finalize: copy final h/c (phase 0 after T=512 even steps) to output tail
// Layout: [outputs | h_fw | c_fw | h_bw | c_bw]
// ---------------------------------------------------------------------------
__global__ void finalize_kernel(float* __restrict__ out) {
    int i = blockIdx.x * blockDim.x + threadIdx.x;
    if (i >= BH) return;
    const size_t base = (size_t)B_ * T_ * 2 * H_;
    out[base + 0 * (size_t)BH + i] = g_h[0][i];            // h_fw
    out[base + 1 * (size_t)BH + i] = g_c[i];               // c_fw
    out[base + 2 * (size_t)BH + i] = g_h[0][BH + i];       // h_bw
    out[base + 3 * (size_t)BH + i] = g_c[BH + i];          // c_bw
}

// ---------------------------------------------------------------------------
// Launch
// ---------------------------------------------------------------------------
extern "C" void kernel_launch(void* const* d_in, const int* in_sizes, int n_in,
                              void* d_out, int out_size) {
    (void)in_sizes; (void)n_in; (void)out_size;
    const float* x       = (const float*)d_in[0];
    const float* w_ih_fw = (const float*)d_in[1];
    const float* w_hh_fw = (const float*)d_in[2];
    const float* b_ih_fw = (const float*)d_in[3];
    const float* b_hh_fw = (const float*)d_in[4];
    const float* w_ih_bw = (const float*)d_in[5];
    const float* w_hh_bw = (const float*)d_in[6];
    const float* b_ih_bw = (const float*)d_in[7];
    const float* b_hh_bw = (const float*)d_in[8];
    float* out = (float*)d_out;

    init_state_kernel<<<(2 * BH + 255) / 256, 256>>>();

    dim3 gproj(64, T_, 2);
    input_proj_kernel<<<gproj, 128>>>(x, w_ih_fw, w_ih_bw,
                                      b_ih_fw, b_hh_fw, b_ih_bw, b_hh_bw);

    for (int t = 0; t < T_; t++) {
        lstm_step_kernel<<<128, 128>>>(w_hh_fw, w_hh_bw, out, t);
    }

    finalize_kernel<<<(BH + 255) / 256, 256>>>(out);
}

// round 2
// speedup vs baseline: 2.1945x; 2.1945x over previous
#include <cuda_runtime.h>
#include <cuda_bf16.h>
#include <math.h>

// Problem constants
#define B_  64
#define T_  512
#define I_  512
#define H_  1024
#define G4  4096           // 4*H
#define BH  (B_*H_)        // 65536

typedef unsigned long long u64;
typedef unsigned int u32;

// ---------------------------------------------------------------------------
// Device scratch
// ---------------------------------------------------------------------------
__device__ float g_xp[(size_t)2 * T_ * B_ * G4];     // xp[dir][t][b][g]  (1 GiB)
__device__ float g_wT[2][H_][G4];                    // w_hh transposed: [dir][k][n] (32 MB)
__device__ float g_hT[2][2][H_][B_];                 // h transposed: [phase][dir][j][b]
__device__ float g_cT[2][H_][B_];                    // c transposed: [dir][j][b]

// ---------------------------------------------------------------------------
// PTX helpers: packed fp32 FMA + cp.async
// ---------------------------------------------------------------------------
__device__ __forceinline__ void fma2(u64& c, u64 a, u64 b) {
    asm volatile("fma.rn.f32x2 %0, %1, %2, %0;" : "+l"(c) : "l"(a), "l"(b));
}
__device__ __forceinline__ u64 rep2(float x) {
    u64 r;
    asm volatile("mov.b64 %0, {%1, %1};" : "=l"(r) : "f"(x));
    return r;
}
__device__ __forceinline__ void cp_async16(u32 smem_addr, const void* gptr) {
    asm volatile("cp.async.cg.shared.global [%0], [%1], 16;" :: "r"(smem_addr), "l"(gptr));
}
__device__ __forceinline__ void cp_commit()  { asm volatile("cp.async.commit_group;"); }
__device__ __forceinline__ void cp_wait1()   { asm volatile("cp.async.wait_group 1;"); }
__device__ __forceinline__ void cp_wait0()   { asm volatile("cp.async.wait_group 0;"); }

__device__ __forceinline__ float lo32(u64 v) { return __uint_as_float((u32)(v & 0xffffffffull)); }
__device__ __forceinline__ float hi32(u64 v) { return __uint_as_float((u32)(v >> 32)); }

// ---------------------------------------------------------------------------
// Init: zero h(phase 0) and c
// ---------------------------------------------------------------------------
__global__ void init_state_kernel() {
    int i = blockIdx.x * blockDim.x + threadIdx.x;
    if (i < 2 * BH) {
        ((float*)g_hT)[i] = 0.0f;     // phase 0 (first 2*BH floats of g_hT)
        ((float*)g_cT)[i] = 0.0f;
    }
}

// ---------------------------------------------------------------------------
// Transpose w_hh [4096, 1024] -> g_wT [dir][1024][4096]
// ---------------------------------------------------------------------------
__global__ void __launch_bounds__(256) transpose_w_kernel(
    const float* __restrict__ wfw, const float* __restrict__ wbw)
{
    __shared__ float tile[32][33];
    const int dir = blockIdx.z;
    const float* w = dir ? wbw : wfw;
    const int n0 = blockIdx.x * 32;        // 0..4095 (row of w)
    const int k0 = blockIdx.y * 32;        // 0..1023 (col of w)
    const int tx = threadIdx.x & 31, ty = threadIdx.x >> 5;   // 32 x 8
#pragma unroll
    for (int r = 0; r < 32; r += 8)
        tile[ty + r][tx] = w[(size_t)(n0 + ty + r) * H_ + k0 + tx];
    __syncthreads();
#pragma unroll
    for (int r = 0; r < 32; r += 8)
        g_wT[dir][k0 + ty + r][n0 + tx] = tile[tx][ty + r];
}

// ---------------------------------------------------------------------------
// Input projection (f32x2 compute): xp = x @ w_ih^T + (b_ih + b_hh)
// CTA = (gtile 64 cols, t, dir); tile 64x64, K=512, 128 threads, 8x4 micro.
// ---------------------------------------------------------------------------
__global__ void __launch_bounds__(128) input_proj_kernel(
    const float* __restrict__ x,
    const float* __restrict__ w_fw, const float* __restrict__ w_bw,
    const float* __restrict__ bi_fw, const float* __restrict__ bh_fw,
    const float* __restrict__ bi_bw, const float* __restrict__ bh_bw)
{
    const int gt  = blockIdx.x;    // 0..63
    const int t   = blockIdx.y;    // 0..511
    const int dir = blockIdx.z;    // 0..1

    const float* w     = dir ? w_bw : w_fw;
    const float* bi    = dir ? bi_bw : bi_fw;
    const float* bh    = dir ? bh_bw : bh_fw;
    const int    src_t = dir ? (T_ - 1 - t) : t;

    __shared__ float sA[16][68];   // [k][b]
    __shared__ float sB[16][68];   // [k][g_local]

    const int tid = threadIdx.x;
    const int tr  = tid >> 4;      // 0..7
    const int tc  = tid & 15;      // 0..15

    u64 acc[4][4];
#pragma unroll
    for (int p = 0; p < 4; p++)
#pragma unroll
        for (int j = 0; j < 4; j++) acc[p][j] = 0ull;

    const float* Abase = x + (size_t)src_t * I_;
    const float* Bbase = w + (size_t)(gt * 64) * I_;

    for (int k0 = 0; k0 < I_; k0 += 16) {
#pragma unroll 4
        for (int idx = tid; idx < 1024; idx += 128) {
            int kk = idx & 15, m = idx >> 4;
            sA[kk][m] = Abase[(size_t)m * (T_ * I_) + k0 + kk];
        }
#pragma unroll 4
        for (int idx = tid; idx < 1024; idx += 128) {
            int kk = idx & 15, n = idx >> 4;
            sB[kk][n] = Bbase[(size_t)n * I_ + k0 + kk];
        }
        __syncthreads();
#pragma unroll
        for (int kk = 0; kk < 16; kk++) {
            const float* ap = &sA[kk][tr * 8];
            u64 a0 = *(const u64*)(ap + 0);
            u64 a1 = *(const u64*)(ap + 2);
            u64 a2 = *(const u64*)(ap + 4);
            u64 a3 = *(const u64*)(ap + 6);
            float4 b4 = *(const float4*)&sB[kk][tc * 4];
            u64 b0 = rep2(b4.x), b1 = rep2(b4.y), b2 = rep2(b4.z), b3 = rep2(b4.w);
            fma2(acc[0][0], a0, b0); fma2(acc[0][1], a0, b1); fma2(acc[0][2], a0, b2); fma2(acc[0][3], a0, b3);
            fma2(acc[1][0], a1, b0); fma2(acc[1][1], a1, b1); fma2(acc[1][2], a1, b2); fma2(acc[1][3], a1, b3);
            fma2(acc[2][0], a2, b0); fma2(acc[2][1], a2, b1); fma2(acc[2][2], a2, b2); fma2(acc[2][3], a2, b3);
            fma2(acc[3][0], a3, b0); fma2(acc[3][1], a3, b1); fma2(acc[3][2], a3, b2); fma2(acc[3][3], a3, b3);
        }
        __syncthreads();
    }

    const int gbase = gt * 64 + tc * 4;
    float bias[4];
#pragma unroll
    for (int j = 0; j < 4; j++) bias[j] = bi[gbase + j] + bh[gbase + j];

    float* outp = g_xp + (((size_t)dir * T_ + t) * B_) * G4;
#pragma unroll
    for (int i = 0; i < 8; i++) {
        int m = tr * 8 + i;
        int p = i >> 1;
        float v0 = (i & 1) ? hi32(acc[p][0]) : lo32(acc[p][0]);
        float v1 = (i & 1) ? hi32(acc[p][1]) : lo32(acc[p][1]);
        float v2 = (i & 1) ? hi32(acc[p][2]) : lo32(acc[p][2]);
        float v3 = (i & 1) ? hi32(acc[p][3]) : lo32(acc[p][3]);
        float4 v = make_float4(v0 + bias[0], v1 + bias[1], v2 + bias[2], v3 + bias[3]);
        *(float4*)(outp + (size_t)m * G4 + gbase) = v;
    }
}

// ---------------------------------------------------------------------------
// LSTM step t. CTA = (dir, jt): gate columns {q*H + jt*16 + jj}, tile 64x64,
// K=1024, f32x2 math, cp.async double-buffered stages, fused activation.
// ---------------------------------------------------------------------------
__global__ void __launch_bounds__(128) lstm_step_kernel(float* __restrict__ out, int t)
{
    const int bx  = blockIdx.x;    // 0..127
    const int dir = bx & 1;
    const int jt  = bx >> 1;       // 0..63

    const int    phase = t & 1;
    const float* hT    = &g_hT[phase][dir][0][0];       // [1024][64] contiguous
    float*       hTn   = &g_hT[phase ^ 1][dir][0][0];
    float*       cT    = &g_cT[dir][0][0];
    const float* wT    = &g_wT[dir][0][0];              // [1024][4096]
    const float* xp    = g_xp + ((size_t)dir * T_ + t) * B_ * G4;

    __shared__ float sA[2][16 * 64];   // stage buffers: [kk][m], m contiguous
    __shared__ float sB[2][16 * 64];   // [kk][n_local], n_local contiguous
    __shared__ float sG[64][65];       // gate staging (stride 65: conflict-free)

    const int tid = threadIdx.x;
    const int tr  = tid >> 4;      // 0..7
    const int tc  = tid & 15;      // 0..15

    // cp.async smem base addresses
    const u32 sA_u32 = (u32)__cvta_generic_to_shared(&sA[0][0]);
    const u32 sB_u32 = (u32)__cvta_generic_to_shared(&sB[0][0]);

    // precomputed src pieces for the B stage (this thread's 2 chunks)
    // chunk c in [0,256): kk=c>>4, piece=c&15, q=piece>>2, part=piece&3
    // gmem col = q*1024 + jt*16 + part*4 ; smem float idx = kk*64 + piece*4

    u64 acc[4][4];
#pragma unroll
    for (int p = 0; p < 4; p++)
#pragma unroll
        for (int j = 0; j < 4; j++) acc[p][j] = 0ull;

    // ---- issue stage 0 ----
    {
        const int k0 = 0;
        // A: contiguous memcpy of 1024 floats from hT + k0*64
        cp_async16(sA_u32 + tid * 16,        hT + k0 * 64 + tid * 4);
        cp_async16(sA_u32 + tid * 16 + 2048, hT + k0 * 64 + tid * 4 + 512);
#pragma unroll
        for (int h = 0; h < 2; h++) {
            int c = tid + h * 128;
            int kk = c >> 4, piece = c & 15;
            int q = piece >> 2, part = piece & 3;
            cp_async16(sB_u32 + (kk * 64 + piece * 4) * 4,
                       wT + (size_t)(k0 + kk) * G4 + q * H_ + jt * 16 + part * 4);
        }
        cp_commit();
    }

    for (int s = 0; s < 64; s++) {
        const int buf = s & 1;
        if (s + 1 < 64) {
            const int k0 = (s + 1) * 16;
            const int nbuf = (s + 1) & 1;
            const u32 a_dst = sA_u32 + nbuf * 4096;
            const u32 b_dst = sB_u32 + nbuf * 4096;
            cp_async16(a_dst + tid * 16,        hT + k0 * 64 + tid * 4);
            cp_async16(a_dst + tid * 16 + 2048, hT + k0 * 64 + tid * 4 + 512);
#pragma unroll
            for (int h = 0; h < 2; h++) {
                int c = tid + h * 128;
                int kk = c >> 4, piece = c & 15;
                int q = piece >> 2, part = piece & 3;
                cp_async16(b_dst + (kk * 64 + piece * 4) * 4,
                           wT + (size_t)(k0 + kk) * G4 + q * H_ + jt * 16 + part * 4);
            }
            cp_commit();
            cp_wait1();
        } else {
            cp_wait0();
        }
        __syncthreads();

        const float* A = &sA[buf][0];
        const float* Bm = &sB[buf][0];
#pragma unroll
        for (int kk = 0; kk < 16; kk++) {
            const float* ap = A + kk * 64 + tr * 8;
            u64 a0 = *(const u64*)(ap + 0);
            u64 a1 = *(const u64*)(ap + 2);
            u64 a2 = *(const u64*)(ap + 4);
            u64 a3 = *(const u64*)(ap + 6);
            float4 b4 = *(const float4*)(Bm + kk * 64 + tc * 4);
            u64 b0 = rep2(b4.x), b1 = rep2(b4.y), b2 = rep2(b4.z), b3 = rep2(b4.w);
            fma2(acc[0][0], a0, b0); fma2(acc[0][1], a0, b1); fma2(acc[0][2], a0, b2); fma2(acc[0][3], a0, b3);
            fma2(acc[1][0], a1, b0); fma2(acc[1][1], a1, b1); fma2(acc[1][2], a1, b2); fma2(acc[1][3], a1, b3);
            fma2(acc[2][0], a2, b0); fma2(acc[2][1], a2, b1); fma2(acc[2][2], a2, b2); fma2(acc[2][3], a2, b3);
            fma2(acc[3][0], a3, b0); fma2(acc[3][1], a3, b1); fma2(acc[3][2], a3, b2); fma2(acc[3][3], a3, b3);
        }
        __syncthreads();
    }

    // ---- stage gates (+xp) into smem ----
    {
        const int q  = tc >> 2;
        const int jj = (tc & 3) * 4;
        const int gcol = q * H_ + jt * 16 + jj;
        const int scol = q * 16 + jj;           // matches sB n_local ordering
#pragma unroll
        for (int i = 0; i < 8; i++) {
            int m = tr * 8 + i;
            int p = i >> 1;
            float4 xv = *(const float4*)(xp + (size_t)m * G4 + gcol);
            float v0 = (i & 1) ? hi32(acc[p][0]) : lo32(acc[p][0]);
            float v1 = (i & 1) ? hi32(acc[p][1]) : lo32(acc[p][1]);
            float v2 = (i & 1) ? hi32(acc[p][2]) : lo32(acc[p][2]);
            float v3 = (i & 1) ? hi32(acc[p][3]) : lo32(acc[p][3]);
            sG[m][scol + 0] = v0 + xv.x;
            sG[m][scol + 1] = v1 + xv.y;
            sG[m][scol + 2] = v2 + xv.z;
            sG[m][scol + 3] = v3 + xv.w;
        }
    }
    __syncthreads();

    // ---- activation + state update (j fast within 16 lanes -> out coalesced 64B) ----
#pragma unroll
    for (int p = tid; p < 1024; p += 128) {
        int b = p >> 4, j = p & 15;
        float ig = sG[b][j];
        float fg = sG[b][16 + j];
        float gg = sG[b][32 + j];
        float og = sG[b][48 + j];
        int jc = jt * 16 + j;

        float c_old = cT[jc * B_ + b];
        float si = 1.0f / (1.0f + __expf(-ig));
        float sf = 1.0f / (1.0f + __expf(-fg));
        float so = 1.0f / (1.0f + __expf(-og));
        float cn = sf * c_old + si * tanhf(gg);
        float hn = so * tanhf(cn);

        cT[jc * B_ + b]  = cn;
        hTn[jc * B_ + b] = hn;
        out[((size_t)b * T_ + t) * (2 * H_) + dir * H_ + jc] = hn;
    }
}

// ---------------------------------------------------------------------------
// Finalize: output tail = [h_fw | c_fw | h_bw | c_bw], each [B, H]
// final h lives in phase 0 (after 512 steps)
// ---------------------------------------------------------------------------
__global__ void finalize_kernel(float* __restrict__ out) {
    int i = blockIdx.x * blockDim.x + threadIdx.x;
    if (i >= BH) return;
    int b = i >> 10, j = i & 1023;
    const size_t base = (size_t)B_ * T_ * 2 * H_;
    out[base + 0 * (size_t)BH + i] = g_hT[0][0][j][b];   // h_fw
    out[base + 1 * (size_t)BH + i] = g_cT[0][j][b];      // c_fw
    out[base + 2 * (size_t)BH + i] = g_hT[0][1][j][b];   // h_bw
    out[base + 3 * (size_t)BH + i] = g_cT[1][j][b];      // c_bw
}

// ---------------------------------------------------------------------------
// Launch
// ---------------------------------------------------------------------------
extern "C" void kernel_launch(void* const* d_in, const int* in_sizes, int n_in,
                              void* d_out, int out_size) {
    (void)in_sizes; (void)n_in; (void)out_size;
    const float* x       = (const float*)d_in[0];
    const float* w_ih_fw = (const float*)d_in[1];
    const float* w_hh_fw = (const float*)d_in[2];
    const float* b_ih_fw = (const float*)d_in[3];
    const float* b_hh_fw = (const float*)d_in[4];
    const float* w_ih_bw = (const float*)d_in[5];
    const float* w_hh_bw = (const float*)d_in[6];
    const float* b_ih_bw = (const float*)d_in[7];
    const float* b_hh_bw = (const float*)d_in[8];
    float* out = (float*)d_out;

    init_state_kernel<<<(2 * BH + 255) / 256, 256>>>();

    dim3 gtw(G4 / 32, H_ / 32, 2);
    transpose_w_kernel<<<gtw, 256>>>(w_hh_fw, w_hh_bw);

    dim3 gproj(64, T_, 2);
    input_proj_kernel<<<gproj, 128>>>(x, w_ih_fw, w_ih_bw,
                                      b_ih_fw, b_hh_fw, b_ih_bw, b_hh_bw);

    for (int t = 0; t < T_; t++) {
        lstm_step_kernel<<<128, 128>>>(out, t);
    }

    finalize_kernel<<<(BH + 255) / 256, 256>>>(out);
}